// round 2
// baseline (speedup 1.0000x reference)
#include <cuda_runtime.h>
#include <math.h>

// ---------------------------------------------------------------------------
// HardConstrainedMLP: MLP forward + 1000 iterations of DRS splitting.
// Reformulation: proj_pinv(s) = s @ P + Q with
//   P = I - Aaug^T @ Aaug_inv^T   (500x500 constant)
//   Q = bv @ Aaug_inv^T           (1024x500, per-batch constant)
// Each batch row is independent across all iterations -> persistent kernel,
// each CTA owns 8 rows, state lives in shared memory, no global sync.
// ---------------------------------------------------------------------------

#define BATCH       1024
#define MDIM        250      // M == N == 250
#define DTOT        500      // M + N
#define HDIM        512
#define NITER       1000
#define PLD         512      // padded leading dim of P (zero-padded cols 500..511)
#define KC          84       // rows of P cached in shared memory
#define ROWS_PER_CTA 8
#define SOLVER_CTAS (BATCH / ROWS_PER_CTA)   // 128

static const float OMEGA_F  = 1.8f;
static const float ALPHA_F  = 1.0f / 1.2f;        // 1/(1+2*sigma)
// y scale = 2*sigma/(1+2*sigma) = 1/6, applied in GEMM epilogue mode 2

// Scratch (zero-initialized device globals; no allocation at runtime)
__device__ float g_Xin[BATCH * DTOT];
__device__ float g_X1 [BATCH * HDIM];
__device__ float g_X2 [BATCH * HDIM];
__device__ float g_Ys [BATCH * DTOT];   // (x@W3+b3) * (1/6)
__device__ float g_Q  [BATCH * DTOT];
__device__ float g_P  [DTOT * PLD];     // padded; cols 500..511 stay zero
__device__ float g_AT [DTOT * MDIM];    // Aaug^T (500x250)

// ---------------------------------------------------------------------------
// Generic tiled GEMM for the (once-per-launch) precompute stage.
//   C[m,n] = f( sum_k A[m,k] * B(k,n) + bias[n] )
//   bT==0: B is KxN row-major;  bT==1: B is NxK row-major (B^T access)
//   mode: 0 none, 1 relu, 2 scale 1/6, 3 identity-minus (C = (m==n) - acc)
// ---------------------------------------------------------------------------
__global__ void gemm_kernel(const float* __restrict__ A, const float* __restrict__ B,
                            const float* __restrict__ bias, float* __restrict__ C,
                            int M, int N, int K, int ldc, int mode, int bT)
{
    __shared__ float As[16][64];
    __shared__ float Bs[16][68];   // padded vs bank conflicts
    const int tid = threadIdx.x;
    const int tx = tid & 15, ty = tid >> 4;
    const int m0 = blockIdx.y * 64, n0 = blockIdx.x * 64;

    float acc[4][4];
    #pragma unroll
    for (int i = 0; i < 4; i++)
        #pragma unroll
        for (int j = 0; j < 4; j++) acc[i][j] = 0.f;

    for (int k0 = 0; k0 < K; k0 += 16) {
        #pragma unroll
        for (int i = 0; i < 4; i++) {
            int idx = tid + i * 256;
            int mr = idx >> 4, kk = idx & 15;
            int mg = m0 + mr, kg = k0 + kk;
            As[kk][mr] = (mg < M && kg < K) ? A[(size_t)mg * K + kg] : 0.f;
        }
        #pragma unroll
        for (int i = 0; i < 4; i++) {
            int idx = tid + i * 256;
            if (!bT) {
                int kk = idx >> 6, cg = idx & 63;
                int kgl = k0 + kk, cgl = n0 + cg;
                Bs[kk][cg] = (kgl < K && cgl < N) ? B[(size_t)kgl * N + cgl] : 0.f;
            } else {
                int cg = idx >> 4, kk = idx & 15;
                int kgl = k0 + kk, cgl = n0 + cg;
                Bs[kk][cg] = (kgl < K && cgl < N) ? B[(size_t)cgl * K + kgl] : 0.f;
            }
        }
        __syncthreads();
        #pragma unroll
        for (int kk = 0; kk < 16; kk++) {
            float a[4], bb[4];
            #pragma unroll
            for (int i = 0; i < 4; i++) a[i] = As[kk][ty * 4 + i];
            #pragma unroll
            for (int j = 0; j < 4; j++) bb[j] = Bs[kk][tx * 4 + j];
            #pragma unroll
            for (int i = 0; i < 4; i++)
                #pragma unroll
                for (int j = 0; j < 4; j++) acc[i][j] += a[i] * bb[j];
        }
        __syncthreads();
    }

    #pragma unroll
    for (int i = 0; i < 4; i++) {
        int mg = m0 + ty * 4 + i;
        if (mg >= M) continue;
        #pragma unroll
        for (int j = 0; j < 4; j++) {
            int ng = n0 + tx * 4 + j;
            if (ng >= N) continue;
            float v = acc[i][j];
            if (bias) v += bias[ng];
            if (mode == 1)      v = fmaxf(v, 0.f);
            else if (mode == 2) v *= (1.0f / 6.0f);
            else if (mode == 3) v = ((mg == ng) ? 1.f : 0.f) - v;
            C[(size_t)mg * ldc + ng] = v;
        }
    }
}

__global__ void concat_kernel(const float* __restrict__ b, const float* __restrict__ cin,
                              float* __restrict__ x)
{
    int idx = blockIdx.x * blockDim.x + threadIdx.x;
    if (idx < BATCH * DTOT) {
        int i = idx / DTOT, j = idx - i * DTOT;
        x[idx] = (j < MDIM) ? b[i * MDIM + j] : cin[i * MDIM + (j - MDIM)];
    }
}

__global__ void transpose_kernel(const float* __restrict__ src, float* __restrict__ dst)
{
    // src = Aaug (250 x 500) row-major; dst = Aaug^T (500 x 250)
    int idx = blockIdx.x * blockDim.x + threadIdx.x;
    if (idx < MDIM * DTOT) {
        int m = idx / DTOT, j = idx - m * DTOT;
        dst[j * MDIM + m] = src[idx];
    }
}

// ---------------------------------------------------------------------------
// Persistent solver: each CTA owns 8 batch rows; 1000 iterations in smem.
// smem layout (floats): S[8*500] Q[8*500] Ys[8*500] TP[8*256] nrm[8] t[8] pad
//                       Pcache[KC*512]
// ---------------------------------------------------------------------------
#define SMEM_FLOATS (14080 + KC * PLD)
#define SMEM_BYTES  (SMEM_FLOATS * 4)

__device__ __forceinline__ float soc_elem(float tp, int c, float nu, float tt)
{
    if (c < MDIM) return tp;            // first N columns: identity
    if (nu <= tt) return tp;            // inside cone
    if (nu <= -tt) return 0.f;          // polar cone
    float h = 0.5f * (tt + nu);
    return (c == DTOT - 1) ? h : h * tp / (nu + 1e-12f);
}

__global__ void __launch_bounds__(256, 1) solver_kernel(float* __restrict__ out)
{
    extern __shared__ float sm[];
    float* Ssm = sm;                 // 4000
    float* Qsm = sm + 4000;          // 4000
    float* Ysm = sm + 8000;          // 4000
    float* TPs = sm + 12000;         // 8*256
    float* nrm = sm + 14048;         // 8
    float* tls = sm + 14056;         // 8
    float* Pcs = sm + 14080;         // KC*512

    const int t = threadIdx.x;
    const int row0 = blockIdx.x * ROWS_PER_CTA;

    // startup: init state + cache Q/Ys + first KC rows of P
    for (int i = t; i < ROWS_PER_CTA * DTOT; i += 256) {
        int r = i / DTOT, cc = i - r * DTOT;
        Ssm[i] = 0.f;
        Qsm[i] = g_Q[(row0 + r) * DTOT + cc];
        Ysm[i] = g_Ys[(row0 + r) * DTOT + cc];
    }
    {
        const float4* Pg4 = reinterpret_cast<const float4*>(g_P);
        float4* Pc4 = reinterpret_cast<float4*>(Pcs);
        for (int i = t; i < KC * PLD / 4; i += 256) Pc4[i] = Pg4[i];
    }
    __syncthreads();

    const float2* Pg  = reinterpret_cast<const float2*>(g_P);
    const float2* Pc2 = reinterpret_cast<const float2*>(Pcs);
    const int c0 = 2 * t, c1 = 2 * t + 1;
    const bool act = (c0 < DTOT);         // threads 250..255 idle in epilogue
    const int w = t >> 5, lane = t & 31;

    for (int it = 0; it <= NITER; ++it) {
        // z = s @ P + Q : accumulators START from Q (this was the round-1 bug)
        float acc0[8], acc1[8];
        #pragma unroll
        for (int r = 0; r < 8; r++) {
            if (act) { acc0[r] = Qsm[r * DTOT + c0]; acc1[r] = Qsm[r * DTOT + c1]; }
            else     { acc0[r] = 0.f;                acc1[r] = 0.f; }
        }

        // ---- GEMM phase A: P rows in shared memory ----
        #pragma unroll 1
        for (int k = 0; k < KC; k += 4) {
            float4 sv[8];
            #pragma unroll
            for (int r = 0; r < 8; r++)
                sv[r] = *reinterpret_cast<const float4*>(&Ssm[r * DTOT + k]);
            float2 p0 = Pc2[(k + 0) * (PLD / 2) + t];
            float2 p1 = Pc2[(k + 1) * (PLD / 2) + t];
            float2 p2 = Pc2[(k + 2) * (PLD / 2) + t];
            float2 p3 = Pc2[(k + 3) * (PLD / 2) + t];
            #pragma unroll
            for (int r = 0; r < 8; r++) {
                acc0[r] += sv[r].x * p0.x;  acc1[r] += sv[r].x * p0.y;
                acc0[r] += sv[r].y * p1.x;  acc1[r] += sv[r].y * p1.y;
                acc0[r] += sv[r].z * p2.x;  acc1[r] += sv[r].z * p2.y;
                acc0[r] += sv[r].w * p3.x;  acc1[r] += sv[r].w * p3.y;
            }
        }

        // ---- GEMM phase B: remaining P rows streamed from L2, double-buffered ----
        float2 pb[2][8];
        #pragma unroll
        for (int j = 0; j < 8; j++) pb[0][j] = Pg[(KC + j) * (PLD / 2) + t];
        #pragma unroll 1
        for (int g = 0; g < (DTOT - KC) / 8; ++g) {
            const int k = KC + g * 8;
            const int cur = g & 1;
            if (g < (DTOT - KC) / 8 - 1) {
                #pragma unroll
                for (int j = 0; j < 8; j++)
                    pb[cur ^ 1][j] = Pg[(k + 8 + j) * (PLD / 2) + t];
            }
            #pragma unroll
            for (int r = 0; r < 8; r++) {
                float4 sa = *reinterpret_cast<const float4*>(&Ssm[r * DTOT + k]);
                float4 sb = *reinterpret_cast<const float4*>(&Ssm[r * DTOT + k + 4]);
                acc0[r] += sa.x * pb[cur][0].x;  acc1[r] += sa.x * pb[cur][0].y;
                acc0[r] += sa.y * pb[cur][1].x;  acc1[r] += sa.y * pb[cur][1].y;
                acc0[r] += sa.z * pb[cur][2].x;  acc1[r] += sa.z * pb[cur][2].y;
                acc0[r] += sa.w * pb[cur][3].x;  acc1[r] += sa.w * pb[cur][3].y;
                acc0[r] += sb.x * pb[cur][4].x;  acc1[r] += sb.x * pb[cur][4].y;
                acc0[r] += sb.y * pb[cur][5].x;  acc1[r] += sb.y * pb[cur][5].y;
                acc0[r] += sb.z * pb[cur][6].x;  acc1[r] += sb.z * pb[cur][6].y;
                acc0[r] += sb.w * pb[cur][7].x;  acc1[r] += sb.w * pb[cur][7].y;
            }
        }

        // ---- final iteration: Z = proj_pinv(s_K) is the output ----
        if (it == NITER) {
            if (act) {
                #pragma unroll
                for (int r = 0; r < 8; r++) {
                    float2 o; o.x = acc0[r]; o.y = acc1[r];
                    *reinterpret_cast<float2*>(&out[(row0 + r) * DTOT + c0]) = o;
                }
            }
            break;
        }

        // ---- elementwise: toproj = alpha*(2z - s) - ys ----
        float tp0[8], tp1[8];
        #pragma unroll
        for (int r = 0; r < 8; r++) {
            if (act) {
                tp0[r] = ALPHA_F * (2.f * acc0[r] - Ssm[r * DTOT + c0]) - Ysm[r * DTOT + c0];
                tp1[r] = ALPHA_F * (2.f * acc1[r] - Ssm[r * DTOT + c1]) - Ysm[r * DTOT + c1];
                if (c0 >= MDIM) TPs[r * 256 + (c0 - MDIM)] = tp0[r];
                if (c1 >= MDIM) TPs[r * 256 + (c1 - MDIM)] = tp1[r];
            }
        }
        __syncthreads();

        // ---- SOC norm: warp w reduces row w over u = cols 250..498 ----
        {
            float ssq = 0.f;
            for (int j = lane; j < MDIM - 1; j += 32) {
                float v = TPs[w * 256 + j];
                ssq += v * v;
            }
            #pragma unroll
            for (int off = 16; off; off >>= 1)
                ssq += __shfl_down_sync(0xffffffffu, ssq, off);
            if (lane == 0) {
                nrm[w] = sqrtf(ssq);
                tls[w] = TPs[w * 256 + (MDIM - 1)];
            }
        }
        __syncthreads();

        // ---- SOC projection + relaxation update s += omega*(tk - z) ----
        if (act) {
            #pragma unroll
            for (int r = 0; r < 8; r++) {
                float nu = nrm[r], tt = tls[r];
                float tk0 = soc_elem(tp0[r], c0, nu, tt);
                float tk1 = soc_elem(tp1[r], c1, nu, tt);
                Ssm[r * DTOT + c0] += OMEGA_F * (tk0 - acc0[r]);
                Ssm[r * DTOT + c1] += OMEGA_F * (tk1 - acc1[r]);
            }
        }
        __syncthreads();
    }
}

// ---------------------------------------------------------------------------
extern "C" void kernel_launch(void* const* d_in, const int* in_sizes, int n_in,
                              void* d_out, int out_size)
{
    const float* b    = (const float*)d_in[0];
    const float* cin  = (const float*)d_in[1];
    const float* W1   = (const float*)d_in[2];
    const float* b1   = (const float*)d_in[3];
    const float* W2   = (const float*)d_in[4];
    const float* b2   = (const float*)d_in[5];
    const float* W3   = (const float*)d_in[6];
    const float* b3   = (const float*)d_in[7];
    const float* Aaug = (const float*)d_in[8];
    const float* Ainv = (const float*)d_in[9];
    float* out = (float*)d_out;

    float *Xin, *X1, *X2, *Ys, *Q, *P, *AT;
    cudaGetSymbolAddress((void**)&Xin, g_Xin);
    cudaGetSymbolAddress((void**)&X1,  g_X1);
    cudaGetSymbolAddress((void**)&X2,  g_X2);
    cudaGetSymbolAddress((void**)&Ys,  g_Ys);
    cudaGetSymbolAddress((void**)&Q,   g_Q);
    cudaGetSymbolAddress((void**)&P,   g_P);
    cudaGetSymbolAddress((void**)&AT,  g_AT);

    cudaFuncSetAttribute(solver_kernel,
                         cudaFuncAttributeMaxDynamicSharedMemorySize, SMEM_BYTES);

    // MLP forward (once): x = [bv, cv]; X1 = relu(x@W1+b1); X2 = relu(X1@W2+b2)
    // Ys = (X2@W3+b3) * (2*sigma/(1+2*sigma))
    concat_kernel<<<(BATCH * DTOT + 255) / 256, 256>>>(b, cin, Xin);
    gemm_kernel<<<dim3(8, 16), 256>>>(Xin, W1, b1, X1, BATCH, HDIM, DTOT, HDIM, 1, 0);
    gemm_kernel<<<dim3(8, 16), 256>>>(X1,  W2, b2, X2, BATCH, HDIM, HDIM, HDIM, 1, 0);
    gemm_kernel<<<dim3(8, 16), 256>>>(X2,  W3, b3, Ys, BATCH, DTOT, HDIM, DTOT, 2, 0);

    // Q = bv @ Ainv^T  (NT gemm: both operands K-contiguous)
    gemm_kernel<<<dim3(8, 16), 256>>>(b, Ainv, nullptr, Q, BATCH, DTOT, MDIM, DTOT, 0, 1);

    // P = I - Aaug^T @ Ainv^T   (transpose Aaug first, then NT gemm, mode 3)
    transpose_kernel<<<(MDIM * DTOT + 255) / 256, 256>>>(Aaug, AT);
    gemm_kernel<<<dim3(8, 8), 256>>>(AT, Ainv, nullptr, P, DTOT, DTOT, MDIM, PLD, 3, 1);

    // Persistent DRS solver: 1000 iterations, no global sync.
    solver_kernel<<<SOLVER_CTAS, 256, SMEM_BYTES>>>(out);
}

// round 3
// speedup vs baseline: 1.0953x; 1.0953x over previous
#include <cuda_runtime.h>
#include <math.h>

// ---------------------------------------------------------------------------
// HardConstrainedMLP: MLP forward + 1000 iterations of DRS splitting.
//   proj_pinv(s) = s @ P + Q,  P = I - Aaug^T @ Ainv^T (500x500, const),
//   Q = bv @ Ainv^T (1024x500, per-batch const).
// Persistent solver: each CTA owns 8 batch rows; inner GEMM uses packed
// fma.rn.f32x2 (2 FMA per issue slot) with P stored k-pair-interleaved:
//   Pp[(k>>1)*1024 + c*2 + (k&1)]  -> a 16B load at (kpair, 2 cols) yields
// two b64 operands (P[k,c],P[k+1,c]) ready for f32x2 FMA; S pairs are the
// b64 halves of 16B S loads. First KCP k-pairs of P cached in smem.
// ---------------------------------------------------------------------------

#define BATCH       1024
#define MDIM        250
#define DTOT        500
#define HDIM        512
#define NITER       1000
#define KCP         50                 // k-pairs of P cached in smem (=100 k)
#define NG          ((250 - KCP) / 4)  // streamed groups of 4 k-pairs = 50
#define ROWS_PER_CTA 8
#define SOLVER_CTAS (BATCH / ROWS_PER_CTA)

#define OMEGA_F 1.8f
#define ALPHA_F (1.0f / 1.2f)

typedef unsigned long long ull;

// f32x2 packed FMA: d.lo += a.lo*b.lo ; d.hi += a.hi*b.hi (single issue slot)
#define FFMA2(d, a, b) \
    asm("fma.rn.f32x2 %0, %1, %2, %0;" : "+l"(d) : "l"(a), "l"(b))

__device__ __forceinline__ float2 f32x2_unpack(ull v) {
    float2 r;
    asm("mov.b64 {%0, %1}, %2;" : "=f"(r.x), "=f"(r.y) : "l"(v));
    return r;
}

// Scratch (device globals; zero-initialized, no runtime allocation)
__device__ float g_X1 [BATCH * HDIM];
__device__ float g_X2 [BATCH * HDIM];
__device__ float g_Ys [BATCH * DTOT];          // (x@W3+b3) * (1/6)
__device__ float g_Q  [BATCH * DTOT];
__device__ float g_P  [250 * 1024];            // k-pair interleaved, col-padded to 512

// ---------------------------------------------------------------------------
// Precompute GEMM.
//  A-access: aT -> A[kg*M+mg] (A is K x M row-major);  A2 != 0 -> concat(A,A2) on k
//  B-access: bT -> B[ng*K+kg] (NT gemm)
//  mode: 0 none, 1 relu, 2 *(1/6), 4 identity-minus + k-pair-interleaved store
// ---------------------------------------------------------------------------
__global__ void gemm_kernel(const float* __restrict__ A, const float* __restrict__ A2,
                            const float* __restrict__ B, const float* __restrict__ bias,
                            float* __restrict__ C,
                            int M, int N, int K, int mode, int bT, int aT)
{
    __shared__ float As[16][64];
    __shared__ float Bs[16][68];
    const int tid = threadIdx.x;
    const int tx = tid & 15, ty = tid >> 4;
    const int m0 = blockIdx.y * 64, n0 = blockIdx.x * 64;

    float acc[4][4];
    #pragma unroll
    for (int i = 0; i < 4; i++)
        #pragma unroll
        for (int j = 0; j < 4; j++) acc[i][j] = 0.f;

    for (int k0 = 0; k0 < K; k0 += 16) {
        #pragma unroll
        for (int i = 0; i < 4; i++) {
            int idx = tid + i * 256;
            int mr = idx >> 4, kk = idx & 15;
            int mg = m0 + mr, kg = k0 + kk;
            float av = 0.f;
            if (mg < M && kg < K) {
                if (aT)       av = A[(size_t)kg * M + mg];
                else if (A2)  av = (kg < MDIM) ? A[(size_t)mg * MDIM + kg]
                                               : A2[(size_t)mg * MDIM + (kg - MDIM)];
                else          av = A[(size_t)mg * K + kg];
            }
            As[kk][mr] = av;
        }
        #pragma unroll
        for (int i = 0; i < 4; i++) {
            int idx = tid + i * 256;
            if (!bT) {
                int kk = idx >> 6, cg = idx & 63;
                int kgl = k0 + kk, cgl = n0 + cg;
                Bs[kk][cg] = (kgl < K && cgl < N) ? B[(size_t)kgl * N + cgl] : 0.f;
            } else {
                int cg = idx >> 4, kk = idx & 15;
                int kgl = k0 + kk, cgl = n0 + cg;
                Bs[kk][cg] = (kgl < K && cgl < N) ? B[(size_t)cgl * K + kgl] : 0.f;
            }
        }
        __syncthreads();
        #pragma unroll
        for (int kk = 0; kk < 16; kk++) {
            float a[4], bb[4];
            #pragma unroll
            for (int i = 0; i < 4; i++) a[i] = As[kk][ty * 4 + i];
            #pragma unroll
            for (int j = 0; j < 4; j++) bb[j] = Bs[kk][tx * 4 + j];
            #pragma unroll
            for (int i = 0; i < 4; i++)
                #pragma unroll
                for (int j = 0; j < 4; j++) acc[i][j] += a[i] * bb[j];
        }
        __syncthreads();
    }

    #pragma unroll
    for (int i = 0; i < 4; i++) {
        int mg = m0 + ty * 4 + i;
        if (mg >= M) continue;
        #pragma unroll
        for (int j = 0; j < 4; j++) {
            int ng = n0 + tx * 4 + j;
            if (ng >= N) continue;
            float v = acc[i][j];
            if (bias) v += bias[ng];
            if (mode == 1)      v = fmaxf(v, 0.f);
            else if (mode == 2) v *= (1.0f / 6.0f);
            if (mode == 4) {
                v = ((mg == ng) ? 1.f : 0.f) - v;
                C[(size_t)(mg >> 1) * 1024 + ng * 2 + (mg & 1)] = v;
            } else {
                C[(size_t)mg * N + ng] = v;
            }
        }
    }
}

// ---------------------------------------------------------------------------
// Persistent solver.
// smem: S[8*500] | part[64] | nrm[8] | tls[8] | pad->4096 | Pcache[KCP*1024]
// ---------------------------------------------------------------------------
#define SMEM_FLOATS (4096 + KCP * 1024)
#define SMEM_BYTES  (SMEM_FLOATS * 4)

__device__ __forceinline__ float soc_elem(float tp, int c, float nu, float tt)
{
    if (c < MDIM) return tp;
    if (nu <= tt) return tp;
    if (nu <= -tt) return 0.f;
    float h = 0.5f * (tt + nu);
    return (c == DTOT - 1) ? h : h * tp / (nu + 1e-12f);
}

__global__ void __launch_bounds__(256, 1) solver_kernel(float* __restrict__ out)
{
    extern __shared__ float sm[];
    float* Ssm  = sm;            // 4000
    float* part = sm + 4000;     // 64   [warp][row]
    float* nrm  = sm + 4064;     // 8
    float* tls  = sm + 4072;     // 8
    float* Pcs  = sm + 4096;     // KCP*1024

    const int t = threadIdx.x;
    const int w = t >> 5, lane = t & 31;
    const int row0 = blockIdx.x * ROWS_PER_CTA;
    const int c0 = 2 * t;
    const bool act = (c0 < DTOT);

    // per-thread constants + own S columns in registers
    float2 q[8], ys[8], sreg[8];
    #pragma unroll
    for (int r = 0; r < 8; r++) {
        if (act) {
            q[r]  = *reinterpret_cast<const float2*>(&g_Q [(row0 + r) * DTOT + c0]);
            ys[r] = *reinterpret_cast<const float2*>(&g_Ys[(row0 + r) * DTOT + c0]);
        } else { q[r] = make_float2(0.f, 0.f); ys[r] = make_float2(0.f, 0.f); }
        sreg[r] = make_float2(0.f, 0.f);
    }
    for (int i = t; i < ROWS_PER_CTA * DTOT; i += 256) Ssm[i] = 0.f;
    {
        const float4* src = reinterpret_cast<const float4*>(g_P);
        float4* dst = reinterpret_cast<float4*>(Pcs);
        #pragma unroll 1
        for (int i = t; i < KCP * 1024 / 4; i += 256) dst[i] = src[i];
    }
    __syncthreads();

    for (int it = 0; it <= NITER; ++it) {
        ull acc0[8], acc1[8];
        #pragma unroll
        for (int r = 0; r < 8; r++) { acc0[r] = 0ull; acc1[r] = 0ull; }

        // ---- phase A: k-pairs 0..KCP-1 from smem ----
        #pragma unroll 1
        for (int kp = 0; kp < KCP; kp += 2) {
            ulonglong2 pv0 = *reinterpret_cast<const ulonglong2*>(&Pcs[(kp    ) * 1024 + 4 * t]);
            ulonglong2 pv1 = *reinterpret_cast<const ulonglong2*>(&Pcs[(kp + 1) * 1024 + 4 * t]);
            #pragma unroll
            for (int r = 0; r < 8; r++) {
                ulonglong2 sv = *reinterpret_cast<const ulonglong2*>(&Ssm[r * DTOT + 2 * kp]);
                FFMA2(acc0[r], sv.x, pv0.x);  FFMA2(acc1[r], sv.x, pv0.y);
                FFMA2(acc0[r], sv.y, pv1.x);  FFMA2(acc1[r], sv.y, pv1.y);
            }
        }

        // ---- phase B: k-pairs KCP..249 streamed from L2, double-buffered ----
        ulonglong2 pb[2][4];
        #pragma unroll
        for (int j = 0; j < 4; j++)
            pb[0][j] = *reinterpret_cast<const ulonglong2*>(&g_P[(KCP + j) * 1024 + 4 * t]);
        #pragma unroll 1
        for (int g = 0; g < NG; g++) {
            const int cur = g & 1;
            if (g + 1 < NG) {
                #pragma unroll
                for (int j = 0; j < 4; j++)
                    pb[cur ^ 1][j] = *reinterpret_cast<const ulonglong2*>(
                        &g_P[(KCP + (g + 1) * 4 + j) * 1024 + 4 * t]);
            }
            const int kf = 2 * (KCP + 4 * g);   // base float index in S row
            #pragma unroll
            for (int r = 0; r < 8; r++) {
                ulonglong2 sa = *reinterpret_cast<const ulonglong2*>(&Ssm[r * DTOT + kf]);
                ulonglong2 sb = *reinterpret_cast<const ulonglong2*>(&Ssm[r * DTOT + kf + 4]);
                FFMA2(acc0[r], sa.x, pb[cur][0].x);  FFMA2(acc1[r], sa.x, pb[cur][0].y);
                FFMA2(acc0[r], sa.y, pb[cur][1].x);  FFMA2(acc1[r], sa.y, pb[cur][1].y);
                FFMA2(acc0[r], sb.x, pb[cur][2].x);  FFMA2(acc1[r], sb.x, pb[cur][2].y);
                FFMA2(acc0[r], sb.y, pb[cur][3].x);  FFMA2(acc1[r], sb.y, pb[cur][3].y);
            }
        }

        // ---- combine lanes: z = Q + sum of both f32x2 partial lanes ----
        float z0[8], z1[8];
        #pragma unroll
        for (int r = 0; r < 8; r++) {
            float2 u0 = f32x2_unpack(acc0[r]);
            float2 u1 = f32x2_unpack(acc1[r]);
            z0[r] = q[r].x + u0.x + u0.y;
            z1[r] = q[r].y + u1.x + u1.y;
        }

        if (it == NITER) {
            if (act) {
                #pragma unroll
                for (int r = 0; r < 8; r++) {
                    float2 o; o.x = z0[r]; o.y = z1[r];
                    *reinterpret_cast<float2*>(&out[(row0 + r) * DTOT + c0]) = o;
                }
            }
            break;
        }

        // ---- toproj + per-thread ssq contribution ----
        float tp0[8], tp1[8], val[8];
        #pragma unroll
        for (int r = 0; r < 8; r++) {
            float v = 0.f;
            if (act) {
                tp0[r] = ALPHA_F * (2.f * z0[r] - sreg[r].x) - ys[r].x;
                tp1[r] = ALPHA_F * (2.f * z1[r] - sreg[r].y) - ys[r].y;
                if (c0 >= MDIM)                      v += tp0[r] * tp0[r];
                if (c0 + 1 >= MDIM && c0 + 1 != DTOT - 1) v += tp1[r] * tp1[r];
            } else { tp0[r] = 0.f; tp1[r] = 0.f; }
            val[r] = v;
        }
        // warp reduce 8 rows
        #pragma unroll
        for (int off = 16; off; off >>= 1)
            #pragma unroll
            for (int r = 0; r < 8; r++)
                val[r] += __shfl_down_sync(0xffffffffu, val[r], off);
        if (lane == 0) {
            #pragma unroll
            for (int r = 0; r < 8; r++) part[w * 8 + r] = val[r];
        }
        if (t == 249) {
            #pragma unroll
            for (int r = 0; r < 8; r++) tls[r] = tp1[r];   // c1 == 499
        }
        __syncthreads();
        // warp w reduces row w's 8 partials
        if (lane < 8) {
            float s = part[lane * 8 + w];
            #pragma unroll
            for (int off = 4; off; off >>= 1)
                s += __shfl_down_sync(0x000000ffu, s, off);
            if (lane == 0) nrm[w] = sqrtf(s);
        }
        __syncthreads();

        // ---- SOC projection + relaxation; write S back to smem ----
        if (act) {
            #pragma unroll
            for (int r = 0; r < 8; r++) {
                float nu = nrm[r], tt = tls[r];
                float tk0 = soc_elem(tp0[r], c0,     nu, tt);
                float tk1 = soc_elem(tp1[r], c0 + 1, nu, tt);
                sreg[r].x += OMEGA_F * (tk0 - z0[r]);
                sreg[r].y += OMEGA_F * (tk1 - z1[r]);
                *reinterpret_cast<float2*>(&Ssm[r * DTOT + c0]) = sreg[r];
            }
        }
        __syncthreads();
    }
}

// ---------------------------------------------------------------------------
extern "C" void kernel_launch(void* const* d_in, const int* in_sizes, int n_in,
                              void* d_out, int out_size)
{
    const float* b    = (const float*)d_in[0];
    const float* cin  = (const float*)d_in[1];
    const float* W1   = (const float*)d_in[2];
    const float* b1   = (const float*)d_in[3];
    const float* W2   = (const float*)d_in[4];
    const float* b2   = (const float*)d_in[5];
    const float* W3   = (const float*)d_in[6];
    const float* b3   = (const float*)d_in[7];
    const float* Aaug = (const float*)d_in[8];
    const float* Ainv = (const float*)d_in[9];
    float* out = (float*)d_out;

    float *X1, *X2, *Ys, *Q, *P;
    cudaGetSymbolAddress((void**)&X1, g_X1);
    cudaGetSymbolAddress((void**)&X2, g_X2);
    cudaGetSymbolAddress((void**)&Ys, g_Ys);
    cudaGetSymbolAddress((void**)&Q,  g_Q);
    cudaGetSymbolAddress((void**)&P,  g_P);

    cudaFuncSetAttribute(solver_kernel,
                         cudaFuncAttributeMaxDynamicSharedMemorySize, SMEM_BYTES);

    // 5 precompute launches + solver (launch #6 -> ncu -s 5 -c 1 captures it)
    // X1 = relu([b|c] @ W1 + b1)   (concat fused via A2)
    gemm_kernel<<<dim3(8, 16), 256>>>(b, cin, W1, b1, X1, BATCH, HDIM, DTOT, 1, 0, 0);
    // X2 = relu(X1 @ W2 + b2)
    gemm_kernel<<<dim3(8, 16), 256>>>(X1, nullptr, W2, b2, X2, BATCH, HDIM, HDIM, 1, 0, 0);
    // Ys = (X2 @ W3 + b3) / 6
    gemm_kernel<<<dim3(8, 16), 256>>>(X2, nullptr, W3, b3, Ys, BATCH, DTOT, HDIM, 2, 0, 0);
    // Q = bv @ Ainv^T
    gemm_kernel<<<dim3(8, 16), 256>>>(b, nullptr, Ainv, nullptr, Q, BATCH, DTOT, MDIM, 0, 1, 0);
    // P = I - Aaug^T @ Ainv^T  (A read transposed; k-pair interleaved store)
    gemm_kernel<<<dim3(8, 8), 256>>>(Aaug, nullptr, Ainv, nullptr, P, DTOT, DTOT, MDIM, 4, 1, 1);
    // Persistent DRS solver
    solver_kernel<<<SOLVER_CTAS, 256, SMEM_BYTES>>>(out);
}

// round 4
// speedup vs baseline: 1.0957x; 1.0004x over previous
#include <cuda_runtime.h>
#include <math.h>

// ---------------------------------------------------------------------------
// HardConstrainedMLP. proj_pinv(s) = s @ P + Q.
// Launch schedule (for ncu -s 5 -c 1 observability):
//   L1: fused precompute (X1 | Q | P via blockIdx.z)
//   L2: X2 gemm     L3: Ys gemm
//   L4..L7: solver chunks of 250 iterations (S persisted in g_S)
// => launches #4..#7 are ALL solver chunks; any skip offset 0..2 captures one.
// ---------------------------------------------------------------------------

#define BATCH       1024
#define MDIM        250
#define DTOT        500
#define HDIM        512
#define NITER       1000
#define NCHUNK      4
#define CHUNK       (NITER / NCHUNK)
#define KCP         50                 // k-pairs of P cached in smem (=100 k)
#define NG          ((250 - KCP) / 4)  // streamed groups of 4 k-pairs = 50
#define ROWS_PER_CTA 8
#define SOLVER_CTAS (BATCH / ROWS_PER_CTA)

#define OMEGA_F 1.8f
#define ALPHA_F (1.0f / 1.2f)

typedef unsigned long long ull;

#define FFMA2(d, a, b) \
    asm("fma.rn.f32x2 %0, %1, %2, %0;" : "+l"(d) : "l"(a), "l"(b))

__device__ __forceinline__ float2 f32x2_unpack(ull v) {
    float2 r;
    asm("mov.b64 {%0, %1}, %2;" : "=f"(r.x), "=f"(r.y) : "l"(v));
    return r;
}

// Scratch (device globals; zero-initialized, no runtime allocation)
__device__ float g_X1 [BATCH * HDIM];
__device__ float g_X2 [BATCH * HDIM];
__device__ float g_Ys [BATCH * DTOT];
__device__ float g_Q  [BATCH * DTOT];
__device__ float g_S  [BATCH * DTOT];          // chunk-to-chunk solver state
__device__ float g_P  [250 * 1024];            // k-pair interleaved, col-pad 512

// ---------------------------------------------------------------------------
// Precompute GEMM body (device function; static smem).
// ---------------------------------------------------------------------------
__device__ void gemm_dev(const float* __restrict__ A, const float* __restrict__ A2,
                         const float* __restrict__ B, const float* __restrict__ bias,
                         float* __restrict__ C,
                         int M, int N, int K, int mode, int bT, int aT)
{
    __shared__ float As[16][64];
    __shared__ float Bs[16][68];
    const int tid = threadIdx.x;
    const int tx = tid & 15, ty = tid >> 4;
    const int m0 = blockIdx.y * 64, n0 = blockIdx.x * 64;

    float acc[4][4];
    #pragma unroll
    for (int i = 0; i < 4; i++)
        #pragma unroll
        for (int j = 0; j < 4; j++) acc[i][j] = 0.f;

    for (int k0 = 0; k0 < K; k0 += 16) {
        #pragma unroll
        for (int i = 0; i < 4; i++) {
            int idx = tid + i * 256;
            int mr = idx >> 4, kk = idx & 15;
            int mg = m0 + mr, kg = k0 + kk;
            float av = 0.f;
            if (mg < M && kg < K) {
                if (aT)       av = A[(size_t)kg * M + mg];
                else if (A2)  av = (kg < MDIM) ? A[(size_t)mg * MDIM + kg]
                                               : A2[(size_t)mg * MDIM + (kg - MDIM)];
                else          av = A[(size_t)mg * K + kg];
            }
            As[kk][mr] = av;
        }
        #pragma unroll
        for (int i = 0; i < 4; i++) {
            int idx = tid + i * 256;
            if (!bT) {
                int kk = idx >> 6, cg = idx & 63;
                int kgl = k0 + kk, cgl = n0 + cg;
                Bs[kk][cg] = (kgl < K && cgl < N) ? B[(size_t)kgl * N + cgl] : 0.f;
            } else {
                int cg = idx >> 4, kk = idx & 15;
                int kgl = k0 + kk, cgl = n0 + cg;
                Bs[kk][cg] = (kgl < K && cgl < N) ? B[(size_t)cgl * K + kgl] : 0.f;
            }
        }
        __syncthreads();
        #pragma unroll
        for (int kk = 0; kk < 16; kk++) {
            float a[4], bb[4];
            #pragma unroll
            for (int i = 0; i < 4; i++) a[i] = As[kk][ty * 4 + i];
            #pragma unroll
            for (int j = 0; j < 4; j++) bb[j] = Bs[kk][tx * 4 + j];
            #pragma unroll
            for (int i = 0; i < 4; i++)
                #pragma unroll
                for (int j = 0; j < 4; j++) acc[i][j] += a[i] * bb[j];
        }
        __syncthreads();
    }

    #pragma unroll
    for (int i = 0; i < 4; i++) {
        int mg = m0 + ty * 4 + i;
        if (mg >= M) continue;
        #pragma unroll
        for (int j = 0; j < 4; j++) {
            int ng = n0 + tx * 4 + j;
            if (ng >= N) continue;
            float v = acc[i][j];
            if (bias) v += bias[ng];
            if (mode == 1)      v = fmaxf(v, 0.f);
            else if (mode == 2) v *= (1.0f / 6.0f);
            if (mode == 4) {
                v = ((mg == ng) ? 1.f : 0.f) - v;
                C[(size_t)(mg >> 1) * 1024 + ng * 2 + (mg & 1)] = v;
            } else {
                C[(size_t)mg * N + ng] = v;
            }
        }
    }
}

__global__ void gemm_kernel(const float* __restrict__ A, const float* __restrict__ A2,
                            const float* __restrict__ B, const float* __restrict__ bias,
                            float* __restrict__ C,
                            int M, int N, int K, int mode, int bT, int aT)
{
    gemm_dev(A, A2, B, bias, C, M, N, K, mode, bT, aT);
}

// Fused: z=0 -> X1 = relu([b|c]@W1+b1); z=1 -> Q = b@Ainv^T; z=2 -> P (8x8 blocks)
__global__ void precompute_fused(const float* b, const float* cin,
                                 const float* W1, const float* b1,
                                 const float* Aaug, const float* Ainv,
                                 float* X1, float* Q, float* P)
{
    int z = blockIdx.z;
    if (z == 0) {
        gemm_dev(b, cin, W1, b1, X1, BATCH, HDIM, DTOT, 1, 0, 0);
    } else if (z == 1) {
        gemm_dev(b, nullptr, Ainv, nullptr, Q, BATCH, DTOT, MDIM, 0, 1, 0);
    } else {
        if (blockIdx.y >= 8) return;
        gemm_dev(Aaug, nullptr, Ainv, nullptr, P, DTOT, DTOT, MDIM, 4, 1, 1);
    }
}

// ---------------------------------------------------------------------------
// Solver chunk.
// smem: S[8*500] | part[64] | nrm[8] | tls[8] | pad->4096 | Pcache[KCP*1024]
// ---------------------------------------------------------------------------
#define SMEM_FLOATS (4096 + KCP * 1024)
#define SMEM_BYTES  (SMEM_FLOATS * 4)

__device__ __forceinline__ float soc_elem(float tp, int c, float nu, float tt)
{
    if (c < MDIM) return tp;
    if (nu <= tt) return tp;
    if (nu <= -tt) return 0.f;
    float h = 0.5f * (tt + nu);
    return (c == DTOT - 1) ? h : h * tp / (nu + 1e-12f);
}

// z = (s @ P + Q) for this thread's 2 columns x 8 rows
__device__ __forceinline__ void do_gemm(const float* __restrict__ Ssm,
                                        const float* __restrict__ Pcs,
                                        int t, const float2* q,
                                        float* z0, float* z1)
{
    ull acc0[8], acc1[8];
    #pragma unroll
    for (int r = 0; r < 8; r++) { acc0[r] = 0ull; acc1[r] = 0ull; }

    // phase A: k-pairs 0..KCP-1 from smem
    #pragma unroll 1
    for (int kp = 0; kp < KCP; kp += 2) {
        ulonglong2 pv0 = *reinterpret_cast<const ulonglong2*>(&Pcs[(kp    ) * 1024 + 4 * t]);
        ulonglong2 pv1 = *reinterpret_cast<const ulonglong2*>(&Pcs[(kp + 1) * 1024 + 4 * t]);
        #pragma unroll
        for (int r = 0; r < 8; r++) {
            ulonglong2 sv = *reinterpret_cast<const ulonglong2*>(&Ssm[r * DTOT + 2 * kp]);
            FFMA2(acc0[r], sv.x, pv0.x);  FFMA2(acc1[r], sv.x, pv0.y);
            FFMA2(acc0[r], sv.y, pv1.x);  FFMA2(acc1[r], sv.y, pv1.y);
        }
    }

    // phase B: k-pairs KCP..249 streamed from L2, double-buffered
    ulonglong2 pb[2][4];
    #pragma unroll
    for (int j = 0; j < 4; j++)
        pb[0][j] = *reinterpret_cast<const ulonglong2*>(&g_P[(KCP + j) * 1024 + 4 * t]);
    #pragma unroll 1
    for (int g = 0; g < NG; g++) {
        const int cur = g & 1;
        if (g + 1 < NG) {
            #pragma unroll
            for (int j = 0; j < 4; j++)
                pb[cur ^ 1][j] = *reinterpret_cast<const ulonglong2*>(
                    &g_P[(KCP + (g + 1) * 4 + j) * 1024 + 4 * t]);
        }
        const int kf = 2 * (KCP + 4 * g);
        #pragma unroll
        for (int r = 0; r < 8; r++) {
            ulonglong2 sa = *reinterpret_cast<const ulonglong2*>(&Ssm[r * DTOT + kf]);
            ulonglong2 sb = *reinterpret_cast<const ulonglong2*>(&Ssm[r * DTOT + kf + 4]);
            FFMA2(acc0[r], sa.x, pb[cur][0].x);  FFMA2(acc1[r], sa.x, pb[cur][0].y);
            FFMA2(acc0[r], sa.y, pb[cur][1].x);  FFMA2(acc1[r], sa.y, pb[cur][1].y);
            FFMA2(acc0[r], sb.x, pb[cur][2].x);  FFMA2(acc1[r], sb.x, pb[cur][2].y);
            FFMA2(acc0[r], sb.y, pb[cur][3].x);  FFMA2(acc1[r], sb.y, pb[cur][3].y);
        }
    }

    #pragma unroll
    for (int r = 0; r < 8; r++) {
        float2 u0 = f32x2_unpack(acc0[r]);
        float2 u1 = f32x2_unpack(acc1[r]);
        z0[r] = q[r].x + u0.x + u0.y;
        z1[r] = q[r].y + u1.x + u1.y;
    }
}

__global__ void __launch_bounds__(256, 1) solver_kernel(float* __restrict__ out,
                                                        int start_it, int end_it)
{
    extern __shared__ float sm[];
    float* Ssm  = sm;            // 4000
    float* part = sm + 4000;     // 64   [warp][row]
    float* nrm  = sm + 4064;     // 8
    float* tls  = sm + 4072;     // 8
    float* Pcs  = sm + 4096;     // KCP*1024

    const int t = threadIdx.x;
    const int w = t >> 5, lane = t & 31;
    const int row0 = blockIdx.x * ROWS_PER_CTA;
    const int c0 = 2 * t;
    const bool act = (c0 < DTOT);

    float2 q[8], ys[8], sreg[8];
    #pragma unroll
    for (int r = 0; r < 8; r++) {
        if (act) {
            q[r]  = *reinterpret_cast<const float2*>(&g_Q [(row0 + r) * DTOT + c0]);
            ys[r] = *reinterpret_cast<const float2*>(&g_Ys[(row0 + r) * DTOT + c0]);
        } else { q[r] = make_float2(0.f, 0.f); ys[r] = make_float2(0.f, 0.f); }
        sreg[r] = make_float2(0.f, 0.f);
    }

    if (start_it == 0) {
        for (int i = t; i < ROWS_PER_CTA * DTOT; i += 256) Ssm[i] = 0.f;
    } else {
        #pragma unroll
        for (int r = 0; r < 8; r++)
            if (act) sreg[r] = *reinterpret_cast<const float2*>(&g_S[(row0 + r) * DTOT + c0]);
        for (int i = t; i < ROWS_PER_CTA * DTOT; i += 256) {
            int r = i / DTOT, cc = i - r * DTOT;
            Ssm[i] = g_S[(row0 + r) * DTOT + cc];
        }
    }
    {
        const float4* src = reinterpret_cast<const float4*>(g_P);
        float4* dst = reinterpret_cast<float4*>(Pcs);
        #pragma unroll 1
        for (int i = t; i < KCP * 1024 / 4; i += 256) dst[i] = src[i];
    }
    __syncthreads();

    float z0[8], z1[8];
    for (int it = start_it; it < end_it; ++it) {
        do_gemm(Ssm, Pcs, t, q, z0, z1);

        // toproj + ssq partials
        float tp0[8], tp1[8], val[8];
        #pragma unroll
        for (int r = 0; r < 8; r++) {
            float v = 0.f;
            if (act) {
                tp0[r] = ALPHA_F * (2.f * z0[r] - sreg[r].x) - ys[r].x;
                tp1[r] = ALPHA_F * (2.f * z1[r] - sreg[r].y) - ys[r].y;
                if (c0 >= MDIM)                           v += tp0[r] * tp0[r];
                if (c0 + 1 >= MDIM && c0 + 1 != DTOT - 1) v += tp1[r] * tp1[r];
            } else { tp0[r] = 0.f; tp1[r] = 0.f; }
            val[r] = v;
        }
        #pragma unroll
        for (int off = 16; off; off >>= 1)
            #pragma unroll
            for (int r = 0; r < 8; r++)
                val[r] += __shfl_down_sync(0xffffffffu, val[r], off);
        if (lane == 0) {
            #pragma unroll
            for (int r = 0; r < 8; r++) part[w * 8 + r] = val[r];
        }
        if (t == 249) {
            #pragma unroll
            for (int r = 0; r < 8; r++) tls[r] = tp1[r];
        }
        __syncthreads();
        if (lane < 8) {
            float s = part[lane * 8 + w];
            #pragma unroll
            for (int off = 4; off; off >>= 1)
                s += __shfl_down_sync(0x000000ffu, s, off);
            if (lane == 0) nrm[w] = sqrtf(s);
        }
        __syncthreads();

        if (act) {
            #pragma unroll
            for (int r = 0; r < 8; r++) {
                float nu = nrm[r], tt = tls[r];
                float tk0 = soc_elem(tp0[r], c0,     nu, tt);
                float tk1 = soc_elem(tp1[r], c0 + 1, nu, tt);
                sreg[r].x += OMEGA_F * (tk0 - z0[r]);
                sreg[r].y += OMEGA_F * (tk1 - z1[r]);
                *reinterpret_cast<float2*>(&Ssm[r * DTOT + c0]) = sreg[r];
            }
        }
        __syncthreads();
    }

    if (end_it == NITER) {
        // final z = proj_pinv(s_K)
        do_gemm(Ssm, Pcs, t, q, z0, z1);
        if (act) {
            #pragma unroll
            for (int r = 0; r < 8; r++) {
                float2 o; o.x = z0[r]; o.y = z1[r];
                *reinterpret_cast<float2*>(&out[(row0 + r) * DTOT + c0]) = o;
            }
        }
    } else if (act) {
        #pragma unroll
        for (int r = 0; r < 8; r++)
            *reinterpret_cast<float2*>(&g_S[(row0 + r) * DTOT + c0]) = sreg[r];
    }
}

// ---------------------------------------------------------------------------
extern "C" void kernel_launch(void* const* d_in, const int* in_sizes, int n_in,
                              void* d_out, int out_size)
{
    const float* b    = (const float*)d_in[0];
    const float* cin  = (const float*)d_in[1];
    const float* W1   = (const float*)d_in[2];
    const float* b1   = (const float*)d_in[3];
    const float* W2   = (const float*)d_in[4];
    const float* b2   = (const float*)d_in[5];
    const float* W3   = (const float*)d_in[6];
    const float* b3   = (const float*)d_in[7];
    const float* Aaug = (const float*)d_in[8];
    const float* Ainv = (const float*)d_in[9];
    float* out = (float*)d_out;

    float *X1, *X2, *Ys, *Q, *P;
    cudaGetSymbolAddress((void**)&X1, g_X1);
    cudaGetSymbolAddress((void**)&X2, g_X2);
    cudaGetSymbolAddress((void**)&Ys, g_Ys);
    cudaGetSymbolAddress((void**)&Q,  g_Q);
    cudaGetSymbolAddress((void**)&P,  g_P);

    cudaFuncSetAttribute(solver_kernel,
                         cudaFuncAttributeMaxDynamicSharedMemorySize, SMEM_BYTES);

    // L1: X1 | Q | P (independent; fused via blockIdx.z)
    precompute_fused<<<dim3(8, 16, 3), 256>>>(b, cin, W1, b1, Aaug, Ainv, X1, Q, P);
    // L2: X2 = relu(X1 @ W2 + b2)
    gemm_kernel<<<dim3(8, 16), 256>>>(X1, nullptr, W2, b2, X2, BATCH, HDIM, HDIM, 1, 0, 0);
    // L3: Ys = (X2 @ W3 + b3) / 6
    gemm_kernel<<<dim3(8, 16), 256>>>(X2, nullptr, W3, b3, Ys, BATCH, DTOT, HDIM, 2, 0, 0);
    // L4..L7: solver chunks
    for (int ch = 0; ch < NCHUNK; ch++)
        solver_kernel<<<SOLVER_CTAS, 256, SMEM_BYTES>>>(out, ch * CHUNK, (ch + 1) * CHUNK);
}

// round 5
// speedup vs baseline: 1.6987x; 1.5504x over previous
#include <cuda_runtime.h>
#include <math.h>

// ---------------------------------------------------------------------------
// HardConstrainedMLP. proj_pinv(s) = s @ P + Q.
// Solver: 512 threads/CTA (16 warps/SM), thread owns ONE column c=t of 8
// batch rows. f32x2 FMAs over k-pairs; P k-pair interleaved:
//   g_P[kp*1024 + 2c + parity] = P[2kp+parity][c]
// Launch schedule: L1 fused precompute, L2, L3, then L4..L7 solver chunks
// (ncu -s 5 -c 1 lands on a solver chunk).
// ---------------------------------------------------------------------------

#define BATCH       1024
#define MDIM        250
#define DTOT        500
#define HDIM        512
#define NITER       1000
#define NCHUNK      4
#define CHUNK       (NITER / NCHUNK)
#define KCP         50                  // k-pairs of P cached in smem (100 k)
#define NSTEP       ((250 - KCP) / 2)   // streamed 2-kp steps = 100
#define ROWS_PER_CTA 8
#define SOLVER_CTAS (BATCH / ROWS_PER_CTA)
#define NTHR        512

#define OMEGA_F 1.8f
#define ALPHA_F (1.0f / 1.2f)

typedef unsigned long long ull;

#define FFMA2(d, a, b) \
    asm("fma.rn.f32x2 %0, %1, %2, %0;" : "+l"(d) : "l"(a), "l"(b))

__device__ __forceinline__ float2 f32x2_unpack(ull v) {
    float2 r;
    asm("mov.b64 {%0, %1}, %2;" : "=f"(r.x), "=f"(r.y) : "l"(v));
    return r;
}

// Scratch (device globals; zero-initialized, no runtime allocation)
__device__ float g_X1 [BATCH * HDIM];
__device__ float g_X2 [BATCH * HDIM];
__device__ float g_Ys [BATCH * DTOT];
__device__ float g_Q  [BATCH * DTOT];
__device__ float g_S  [BATCH * DTOT];
__device__ float g_P  [250 * 1024];

// ---------------------------------------------------------------------------
// Precompute GEMM body (unchanged from R4).
// ---------------------------------------------------------------------------
__device__ void gemm_dev(const float* __restrict__ A, const float* __restrict__ A2,
                         const float* __restrict__ B, const float* __restrict__ bias,
                         float* __restrict__ C,
                         int M, int N, int K, int mode, int bT, int aT)
{
    __shared__ float As[16][64];
    __shared__ float Bs[16][68];
    const int tid = threadIdx.x;
    const int tx = tid & 15, ty = tid >> 4;
    const int m0 = blockIdx.y * 64, n0 = blockIdx.x * 64;

    float acc[4][4];
    #pragma unroll
    for (int i = 0; i < 4; i++)
        #pragma unroll
        for (int j = 0; j < 4; j++) acc[i][j] = 0.f;

    for (int k0 = 0; k0 < K; k0 += 16) {
        #pragma unroll
        for (int i = 0; i < 4; i++) {
            int idx = tid + i * 256;
            int mr = idx >> 4, kk = idx & 15;
            int mg = m0 + mr, kg = k0 + kk;
            float av = 0.f;
            if (mg < M && kg < K) {
                if (aT)       av = A[(size_t)kg * M + mg];
                else if (A2)  av = (kg < MDIM) ? A[(size_t)mg * MDIM + kg]
                                               : A2[(size_t)mg * MDIM + (kg - MDIM)];
                else          av = A[(size_t)mg * K + kg];
            }
            As[kk][mr] = av;
        }
        #pragma unroll
        for (int i = 0; i < 4; i++) {
            int idx = tid + i * 256;
            if (!bT) {
                int kk = idx >> 6, cg = idx & 63;
                int kgl = k0 + kk, cgl = n0 + cg;
                Bs[kk][cg] = (kgl < K && cgl < N) ? B[(size_t)kgl * N + cgl] : 0.f;
            } else {
                int cg = idx >> 4, kk = idx & 15;
                int kgl = k0 + kk, cgl = n0 + cg;
                Bs[kk][cg] = (kgl < K && cgl < N) ? B[(size_t)cgl * K + kgl] : 0.f;
            }
        }
        __syncthreads();
        #pragma unroll
        for (int kk = 0; kk < 16; kk++) {
            float a[4], bb[4];
            #pragma unroll
            for (int i = 0; i < 4; i++) a[i] = As[kk][ty * 4 + i];
            #pragma unroll
            for (int j = 0; j < 4; j++) bb[j] = Bs[kk][tx * 4 + j];
            #pragma unroll
            for (int i = 0; i < 4; i++)
                #pragma unroll
                for (int j = 0; j < 4; j++) acc[i][j] += a[i] * bb[j];
        }
        __syncthreads();
    }

    #pragma unroll
    for (int i = 0; i < 4; i++) {
        int mg = m0 + ty * 4 + i;
        if (mg >= M) continue;
        #pragma unroll
        for (int j = 0; j < 4; j++) {
            int ng = n0 + tx * 4 + j;
            if (ng >= N) continue;
            float v = acc[i][j];
            if (bias) v += bias[ng];
            if (mode == 1)      v = fmaxf(v, 0.f);
            else if (mode == 2) v *= (1.0f / 6.0f);
            if (mode == 4) {
                v = ((mg == ng) ? 1.f : 0.f) - v;
                C[(size_t)(mg >> 1) * 1024 + ng * 2 + (mg & 1)] = v;
            } else {
                C[(size_t)mg * N + ng] = v;
            }
        }
    }
}

__global__ void gemm_kernel(const float* __restrict__ A, const float* __restrict__ A2,
                            const float* __restrict__ B, const float* __restrict__ bias,
                            float* __restrict__ C,
                            int M, int N, int K, int mode, int bT, int aT)
{
    gemm_dev(A, A2, B, bias, C, M, N, K, mode, bT, aT);
}

__global__ void precompute_fused(const float* b, const float* cin,
                                 const float* W1, const float* b1,
                                 const float* Aaug, const float* Ainv,
                                 float* X1, float* Q, float* P)
{
    int z = blockIdx.z;
    if (z == 0) {
        gemm_dev(b, cin, W1, b1, X1, BATCH, HDIM, DTOT, 1, 0, 0);
    } else if (z == 1) {
        gemm_dev(b, nullptr, Ainv, nullptr, Q, BATCH, DTOT, MDIM, 0, 1, 0);
    } else {
        if (blockIdx.y >= 8) return;
        gemm_dev(Aaug, nullptr, Ainv, nullptr, P, DTOT, DTOT, MDIM, 4, 1, 1);
    }
}

// ---------------------------------------------------------------------------
// Solver. smem: S[4000] | part[128] | nrm[8] | tls[8] | pad->4352 | Pcs[KCP*1024]
// ---------------------------------------------------------------------------
#define SMEM_FLOATS (4352 + KCP * 1024)
#define SMEM_BYTES  (SMEM_FLOATS * 4)

__device__ __forceinline__ float soc_elem(float tp, int c, float nu, float tt)
{
    if (c < MDIM) return tp;
    if (nu <= tt) return tp;
    if (nu <= -tt) return 0.f;
    float h = 0.5f * (tt + nu);
    return (c == DTOT - 1) ? h : h * tp / (nu + 1e-12f);
}

// z[r] = Q[r,c] + sum_k S[r,k] * P[k,c]   (this thread's single column c)
__device__ __forceinline__ void do_gemm(const float* __restrict__ Ssm,
                                        const float* __restrict__ Pcs,
                                        int t, const float* q, float* z)
{
    const int tc2 = 2 * t;
    ull acc[8];
    #pragma unroll
    for (int r = 0; r < 8; r++) acc[r] = 0ull;

    // phase A: cached k-pairs 0..KCP-1 (P from smem; S broadcast LDS.128)
    #pragma unroll 1
    for (int kp = 0; kp < KCP; kp += 2) {
        ull p0 = *reinterpret_cast<const ull*>(&Pcs[kp * 1024 + tc2]);
        ull p1 = *reinterpret_cast<const ull*>(&Pcs[(kp + 1) * 1024 + tc2]);
        #pragma unroll
        for (int r = 0; r < 8; r++) {
            ulonglong2 sv = *reinterpret_cast<const ulonglong2*>(&Ssm[r * DTOT + 2 * kp]);
            FFMA2(acc[r], sv.x, p0);
            FFMA2(acc[r], sv.y, p1);
        }
    }

    // phase B: streamed k-pairs, 4-step (8 x b64) prefetch ring, static slots
    ull pf[8];
    #pragma unroll
    for (int j = 0; j < 8; j++)
        pf[j] = *reinterpret_cast<const ull*>(&g_P[(KCP + j) * 1024 + tc2]);
    #pragma unroll 4
    for (int s = 0; s < NSTEP; s++) {
        const int kp = KCP + 2 * s;
        const int slot = (s & 3) * 2;
        ull p0 = pf[slot], p1 = pf[slot + 1];
        if (s + 4 < NSTEP) {
            pf[slot]     = *reinterpret_cast<const ull*>(&g_P[(kp + 8) * 1024 + tc2]);
            pf[slot + 1] = *reinterpret_cast<const ull*>(&g_P[(kp + 9) * 1024 + tc2]);
        }
        #pragma unroll
        for (int r = 0; r < 8; r++) {
            ulonglong2 sv = *reinterpret_cast<const ulonglong2*>(&Ssm[r * DTOT + 2 * kp]);
            FFMA2(acc[r], sv.x, p0);
            FFMA2(acc[r], sv.y, p1);
        }
    }

    #pragma unroll
    for (int r = 0; r < 8; r++) {
        float2 u = f32x2_unpack(acc[r]);
        z[r] = q[r] + u.x + u.y;
    }
}

__global__ void __launch_bounds__(NTHR, 1) solver_kernel(float* __restrict__ out,
                                                         int start_it, int end_it)
{
    extern __shared__ float sm[];
    float* Ssm  = sm;            // 4000
    float* part = sm + 4000;     // 128  [warp][row]
    float* nrm  = sm + 4128;     // 8
    float* tls  = sm + 4136;     // 8
    float* Pcs  = sm + 4352;     // KCP*1024

    const int t = threadIdx.x;
    const int w = t >> 5, lane = t & 31;
    const int row0 = blockIdx.x * ROWS_PER_CTA;
    const int c = t;
    const bool act = (c < DTOT);

    float q[8], ys[8], sreg[8];
    #pragma unroll
    for (int r = 0; r < 8; r++) {
        if (act) {
            q[r]  = g_Q [(row0 + r) * DTOT + c];
            ys[r] = g_Ys[(row0 + r) * DTOT + c];
        } else { q[r] = 0.f; ys[r] = 0.f; }
        sreg[r] = 0.f;
    }

    if (start_it == 0) {
        for (int i = t; i < ROWS_PER_CTA * DTOT; i += NTHR) Ssm[i] = 0.f;
    } else {
        #pragma unroll
        for (int r = 0; r < 8; r++)
            if (act) sreg[r] = g_S[(row0 + r) * DTOT + c];
        for (int i = t; i < ROWS_PER_CTA * DTOT; i += NTHR) {
            int r = i / DTOT, cc = i - r * DTOT;
            Ssm[i] = g_S[(row0 + r) * DTOT + cc];
        }
    }
    {
        const float4* src = reinterpret_cast<const float4*>(g_P);
        float4* dst = reinterpret_cast<float4*>(Pcs);
        #pragma unroll 1
        for (int i = t; i < KCP * 1024 / 4; i += NTHR) dst[i] = src[i];
    }
    __syncthreads();

    float z[8];
    for (int it = start_it; it < end_it; ++it) {
        do_gemm(Ssm, Pcs, t, q, z);

        // toproj + per-thread ssq contribution (cols 250..498 only)
        float tp[8], val[8];
        const bool in_u = (c >= MDIM) && (c != DTOT - 1);
        #pragma unroll
        for (int r = 0; r < 8; r++) {
            if (act) {
                tp[r] = ALPHA_F * (2.f * z[r] - sreg[r]) - ys[r];
                val[r] = in_u ? tp[r] * tp[r] : 0.f;
            } else { tp[r] = 0.f; val[r] = 0.f; }
        }
        #pragma unroll
        for (int off = 16; off; off >>= 1)
            #pragma unroll
            for (int r = 0; r < 8; r++)
                val[r] += __shfl_down_sync(0xffffffffu, val[r], off);
        if (lane == 0) {
            #pragma unroll
            for (int r = 0; r < 8; r++) part[w * 8 + r] = val[r];
        }
        if (t == DTOT - 1) {
            #pragma unroll
            for (int r = 0; r < 8; r++) tls[r] = tp[r];
        }
        __syncthreads();
        // warp w (w<8) reduces row w's 16 partials
        if (w < 8 && lane < 16) {
            float s = part[lane * 8 + w];
            #pragma unroll
            for (int off = 8; off; off >>= 1)
                s += __shfl_down_sync(0x0000ffffu, s, off);
            if (lane == 0) nrm[w] = sqrtf(s);
        }
        __syncthreads();

        if (act) {
            #pragma unroll
            for (int r = 0; r < 8; r++) {
                float nu = nrm[r], tt = tls[r];
                float tk = soc_elem(tp[r], c, nu, tt);
                sreg[r] += OMEGA_F * (tk - z[r]);
                Ssm[r * DTOT + c] = sreg[r];
            }
        }
        __syncthreads();
    }

    if (end_it == NITER) {
        do_gemm(Ssm, Pcs, t, q, z);
        if (act) {
            #pragma unroll
            for (int r = 0; r < 8; r++)
                out[(row0 + r) * DTOT + c] = z[r];
        }
    } else if (act) {
        #pragma unroll
        for (int r = 0; r < 8; r++)
            g_S[(row0 + r) * DTOT + c] = sreg[r];
    }
}

// ---------------------------------------------------------------------------
extern "C" void kernel_launch(void* const* d_in, const int* in_sizes, int n_in,
                              void* d_out, int out_size)
{
    const float* b    = (const float*)d_in[0];
    const float* cin  = (const float*)d_in[1];
    const float* W1   = (const float*)d_in[2];
    const float* b1   = (const float*)d_in[3];
    const float* W2   = (const float*)d_in[4];
    const float* b2   = (const float*)d_in[5];
    const float* W3   = (const float*)d_in[6];
    const float* b3   = (const float*)d_in[7];
    const float* Aaug = (const float*)d_in[8];
    const float* Ainv = (const float*)d_in[9];
    float* out = (float*)d_out;

    float *X1, *X2, *Ys, *Q, *P;
    cudaGetSymbolAddress((void**)&X1, g_X1);
    cudaGetSymbolAddress((void**)&X2, g_X2);
    cudaGetSymbolAddress((void**)&Ys, g_Ys);
    cudaGetSymbolAddress((void**)&Q,  g_Q);
    cudaGetSymbolAddress((void**)&P,  g_P);

    cudaFuncSetAttribute(solver_kernel,
                         cudaFuncAttributeMaxDynamicSharedMemorySize, SMEM_BYTES);

    precompute_fused<<<dim3(8, 16, 3), 256>>>(b, cin, W1, b1, Aaug, Ainv, X1, Q, P);
    gemm_kernel<<<dim3(8, 16), 256>>>(X1, nullptr, W2, b2, X2, BATCH, HDIM, HDIM, 1, 0, 0);
    gemm_kernel<<<dim3(8, 16), 256>>>(X2, nullptr, W3, b3, Ys, BATCH, DTOT, HDIM, 2, 0, 0);
    for (int ch = 0; ch < NCHUNK; ch++)
        solver_kernel<<<SOLVER_CTAS, NTHR, SMEM_BYTES>>>(out, ch * CHUNK, (ch + 1) * CHUNK);
}